// round 1
// baseline (speedup 1.0000x reference)
#include <cuda_runtime.h>
#include <math_constants.h>

// VectorQuantizer: x [32, 64, 64, 64] fp32, emb [512, 64] fp32.
// For each of N = 32*64*64 = 131072 pixels (channel vectors of length 64,
// channel-strided by H*W = 4096 in memory), find nearest codebook row by
// squared L2 distance, gather that row to the output in [B,C,H,W] layout.
//
// Numerics deliberately mirror the reference:
//   dists = (x_sq + e_sq[k]) - 2*dot   with separate fp32 roundings,
//   x_sq / e_sq as sequential mul-then-add, dot as sequential FMA,
//   argmin = first strict minimum scanning k ascending.

#define VQ_K 512
#define VQ_D 64
#define VQ_HW 4096
#define VQ_NPIX 131072
#define VQ_THREADS 256
#define VQ_SMEM ((VQ_K * VQ_D + VQ_K) * (int)sizeof(float))

__global__ __launch_bounds__(VQ_THREADS, 1)
void vq_kernel(const float* __restrict__ x,
               const float* __restrict__ emb,
               float* __restrict__ out) {
    extern __shared__ float sm[];
    float* es  = sm;               // [512][64] codebook
    float* esq = sm + VQ_K * VQ_D; // [512] squared norms

    const int tid = threadIdx.x;

    // Stage codebook into shared memory (vectorized, coalesced).
    {
        const float4* e4 = reinterpret_cast<const float4*>(emb);
        float4* s4 = reinterpret_cast<float4*>(es);
        #pragma unroll
        for (int i = tid; i < VQ_K * VQ_D / 4; i += VQ_THREADS) {
            s4[i] = e4[i];
        }
    }
    __syncthreads();

    // e_sq: sequential mul-then-add (matches jnp.sum(emb*emb, axis=1) order).
    for (int k = tid; k < VQ_K; k += VQ_THREADS) {
        const float* er = es + k * VQ_D;
        float s = 0.0f;
        #pragma unroll
        for (int c = 0; c < VQ_D; c++) {
            s = __fadd_rn(s, __fmul_rn(er[c], er[c]));
        }
        esq[k] = s;
    }
    __syncthreads();

    const int p  = blockIdx.x * VQ_THREADS + tid;  // pixel id, < 131072
    const int b  = p >> 12;                        // / 4096
    const int hw = p & 4095;                       // % 4096

    const float* xp = x + (size_t)b * VQ_D * VQ_HW + hw;

    // Load this pixel's channel vector into registers (coalesced across warp).
    float xv[VQ_D];
    #pragma unroll
    for (int c = 0; c < VQ_D; c++) {
        xv[c] = xp[(size_t)c * VQ_HW];
    }

    // x_sq: sequential mul-then-add.
    float xsq = 0.0f;
    #pragma unroll
    for (int c = 0; c < VQ_D; c++) {
        xsq = __fadd_rn(xsq, __fmul_rn(xv[c], xv[c]));
    }

    // Argmin over 512 codes; 4 codes per iteration for FMA ILP.
    float best = CUDART_INF_F;
    int   bi   = 0;
    for (int k = 0; k < VQ_K; k += 4) {
        const float* e0 = es + k * VQ_D;
        float a0 = 0.0f, a1 = 0.0f, a2 = 0.0f, a3 = 0.0f;
        #pragma unroll
        for (int c = 0; c < VQ_D; c++) {
            const float xc = xv[c];
            a0 = __fmaf_rn(xc, e0[c            ], a0);
            a1 = __fmaf_rn(xc, e0[c +     VQ_D ], a1);
            a2 = __fmaf_rn(xc, e0[c + 2 * VQ_D ], a2);
            a3 = __fmaf_rn(xc, e0[c + 3 * VQ_D ], a3);
        }
        // dist = fl(fl(xsq + esq) + (-2*acc)), -2*acc is exact (scale by power of 2)
        const float d0 = __fadd_rn(__fadd_rn(xsq, esq[k + 0]), __fmul_rn(-2.0f, a0));
        const float d1 = __fadd_rn(__fadd_rn(xsq, esq[k + 1]), __fmul_rn(-2.0f, a1));
        const float d2 = __fadd_rn(__fadd_rn(xsq, esq[k + 2]), __fmul_rn(-2.0f, a2));
        const float d3 = __fadd_rn(__fadd_rn(xsq, esq[k + 3]), __fmul_rn(-2.0f, a3));
        if (d0 < best) { best = d0; bi = k + 0; }
        if (d1 < best) { best = d1; bi = k + 1; }
        if (d2 < best) { best = d2; bi = k + 2; }
        if (d3 < best) { best = d3; bi = k + 3; }
    }

    // Gather winning code row to output (coalesced across warp per channel).
    float* op = out + (size_t)b * VQ_D * VQ_HW + hw;
    const float* eb = es + bi * VQ_D;
    #pragma unroll
    for (int c = 0; c < VQ_D; c++) {
        op[(size_t)c * VQ_HW] = eb[c];
    }
}

extern "C" void kernel_launch(void* const* d_in, const int* in_sizes, int n_in,
                              void* d_out, int out_size) {
    (void)in_sizes; (void)n_in; (void)out_size;
    const float* x   = (const float*)d_in[0];
    const float* emb = (const float*)d_in[1];
    float* out = (float*)d_out;

    // >48KB dynamic smem requires opting in (idempotent, capture-safe).
    cudaFuncSetAttribute(vq_kernel, cudaFuncAttributeMaxDynamicSharedMemorySize,
                         VQ_SMEM);

    vq_kernel<<<VQ_NPIX / VQ_THREADS, VQ_THREADS, VQ_SMEM>>>(x, emb, out);
}

// round 2
// speedup vs baseline: 2.9290x; 2.9290x over previous
#include <cuda_runtime.h>
#include <math_constants.h>

// VectorQuantizer: x [32, 64, 64, 64] fp32, emb [512, 64] fp32.
// For each of N = 131072 pixels find nearest codebook row (squared L2),
// gather that row to output in [B,C,H,W] layout.
//
// Round-2 structure:
//  - codebook + e_sq staged in shared memory (133 KB, 1 CTA/SM)
//  - 2 pixels per thread (x vectors register-resident, packed as f32x2 pairs)
//  - dot products via packed fma.rn.f32x2 (FFMA2): even-c chain in lane lo,
//    odd-c chain in lane hi, combined with one fp32 add at the end.
//  - codebook read via LDS.128 (ulonglong2 = two f32x2 operands per load)
//  - dist = fl(fl(xsq + esq[k]) + fl(-2*dot)); argmin = first strict min, k asc.

#define VQ_K 512
#define VQ_D 64
#define VQ_HW 4096
#define VQ_NPIX 131072
#define VQ_THREADS 256
#define VQ_HALF (VQ_NPIX / 2)
#define VQ_SMEM ((VQ_K * VQ_D + VQ_K) * (int)sizeof(float))

typedef unsigned long long ull;

__device__ __forceinline__ ull ffma2(ull a, ull b, ull c) {
    ull d;
    asm("fma.rn.f32x2 %0, %1, %2, %3;" : "=l"(d) : "l"(a), "l"(b), "l"(c));
    return d;
}
__device__ __forceinline__ ull pack2(float lo, float hi) {
    ull d;
    asm("mov.b64 %0, {%1, %2};" : "=l"(d) : "f"(lo), "f"(hi));
    return d;
}
__device__ __forceinline__ void unpack2(ull v, float& lo, float& hi) {
    asm("mov.b64 {%0, %1}, %2;" : "=f"(lo), "=f"(hi) : "l"(v));
}

__global__ __launch_bounds__(VQ_THREADS, 1)
void vq_kernel(const float* __restrict__ x,
               const float* __restrict__ emb,
               float* __restrict__ out) {
    extern __shared__ float sm[];
    float* es  = sm;               // [512][64] codebook
    float* esq = sm + VQ_K * VQ_D; // [512]

    const int tid = threadIdx.x;

    // Stage codebook (coalesced float4).
    {
        const float4* e4 = reinterpret_cast<const float4*>(emb);
        float4* s4 = reinterpret_cast<float4*>(es);
        #pragma unroll
        for (int i = tid; i < VQ_K * VQ_D / 4; i += VQ_THREADS) s4[i] = e4[i];
    }
    __syncthreads();

    // e_sq: sequential mul-then-add (unchanged from round 1 — bit-exact vs ref).
    for (int k = tid; k < VQ_K; k += VQ_THREADS) {
        const float* er = es + k * VQ_D;
        float s = 0.0f;
        #pragma unroll
        for (int c = 0; c < VQ_D; c++) s = __fadd_rn(s, __fmul_rn(er[c], er[c]));
        esq[k] = s;
    }
    __syncthreads();

    // Two pixels per thread: p0 in first half, p1 in second half (both coalesced).
    const int p0 = blockIdx.x * VQ_THREADS + tid;
    const int p1 = p0 + VQ_HALF;

    ull xa[VQ_D / 2], xb[VQ_D / 2];
    float xsqa = 0.0f, xsqb = 0.0f;
    {
        const int b0 = p0 >> 12, hw0 = p0 & 4095;
        const float* xp = x + (size_t)b0 * VQ_D * VQ_HW + hw0;
        float prev = 0.0f;
        #pragma unroll
        for (int c = 0; c < VQ_D; c++) {
            const float xc = xp[(size_t)c * VQ_HW];
            xsqa = __fadd_rn(xsqa, __fmul_rn(xc, xc));
            if (c & 1) xa[c >> 1] = pack2(prev, xc); else prev = xc;
        }
    }
    {
        const int b1 = p1 >> 12, hw1 = p1 & 4095;
        const float* xp = x + (size_t)b1 * VQ_D * VQ_HW + hw1;
        float prev = 0.0f;
        #pragma unroll
        for (int c = 0; c < VQ_D; c++) {
            const float xc = xp[(size_t)c * VQ_HW];
            xsqb = __fadd_rn(xsqb, __fmul_rn(xc, xc));
            if (c & 1) xb[c >> 1] = pack2(prev, xc); else prev = xc;
        }
    }

    float best0 = CUDART_INF_F, best1 = CUDART_INF_F;
    int   bi0 = 0, bi1 = 0;

    for (int kb = 0; kb < VQ_K; kb += 4) {
        const ulonglong2* e0 = reinterpret_cast<const ulonglong2*>(es + (kb + 0) * VQ_D);
        const ulonglong2* e1 = reinterpret_cast<const ulonglong2*>(es + (kb + 1) * VQ_D);
        const ulonglong2* e2 = reinterpret_cast<const ulonglong2*>(es + (kb + 2) * VQ_D);
        const ulonglong2* e3 = reinterpret_cast<const ulonglong2*>(es + (kb + 3) * VQ_D);

        // 8 packed accumulators: {even-c sum, odd-c sum} per (pixel, code).
        ull a00 = 0, a01 = 0, a02 = 0, a03 = 0;
        ull a10 = 0, a11 = 0, a12 = 0, a13 = 0;

        #pragma unroll
        for (int j = 0; j < VQ_D / 4; j++) {   // 16 iters, 4 channels each
            const ulonglong2 v0 = e0[j];
            const ulonglong2 v1 = e1[j];
            const ulonglong2 v2 = e2[j];
            const ulonglong2 v3 = e3[j];
            const ull xA0 = xa[2 * j], xA1 = xa[2 * j + 1];
            const ull xB0 = xb[2 * j], xB1 = xb[2 * j + 1];

            a00 = ffma2(xA0, v0.x, a00);
            a01 = ffma2(xA0, v1.x, a01);
            a02 = ffma2(xA0, v2.x, a02);
            a03 = ffma2(xA0, v3.x, a03);
            a10 = ffma2(xB0, v0.x, a10);
            a11 = ffma2(xB0, v1.x, a11);
            a12 = ffma2(xB0, v2.x, a12);
            a13 = ffma2(xB0, v3.x, a13);

            a00 = ffma2(xA1, v0.y, a00);
            a01 = ffma2(xA1, v1.y, a01);
            a02 = ffma2(xA1, v2.y, a02);
            a03 = ffma2(xA1, v3.y, a03);
            a10 = ffma2(xB1, v0.y, a10);
            a11 = ffma2(xB1, v1.y, a11);
            a12 = ffma2(xB1, v2.y, a12);
            a13 = ffma2(xB1, v3.y, a13);
        }

        const float eq0 = esq[kb + 0], eq1 = esq[kb + 1];
        const float eq2 = esq[kb + 2], eq3 = esq[kb + 3];

        float lo, hi, dot, d;

        // pixel 0
        unpack2(a00, lo, hi); dot = __fadd_rn(lo, hi);
        d = __fadd_rn(__fadd_rn(xsqa, eq0), __fmul_rn(-2.0f, dot));
        if (d < best0) { best0 = d; bi0 = kb + 0; }
        unpack2(a01, lo, hi); dot = __fadd_rn(lo, hi);
        d = __fadd_rn(__fadd_rn(xsqa, eq1), __fmul_rn(-2.0f, dot));
        if (d < best0) { best0 = d; bi0 = kb + 1; }
        unpack2(a02, lo, hi); dot = __fadd_rn(lo, hi);
        d = __fadd_rn(__fadd_rn(xsqa, eq2), __fmul_rn(-2.0f, dot));
        if (d < best0) { best0 = d; bi0 = kb + 2; }
        unpack2(a03, lo, hi); dot = __fadd_rn(lo, hi);
        d = __fadd_rn(__fadd_rn(xsqa, eq3), __fmul_rn(-2.0f, dot));
        if (d < best0) { best0 = d; bi0 = kb + 3; }

        // pixel 1
        unpack2(a10, lo, hi); dot = __fadd_rn(lo, hi);
        d = __fadd_rn(__fadd_rn(xsqb, eq0), __fmul_rn(-2.0f, dot));
        if (d < best1) { best1 = d; bi1 = kb + 0; }
        unpack2(a11, lo, hi); dot = __fadd_rn(lo, hi);
        d = __fadd_rn(__fadd_rn(xsqb, eq1), __fmul_rn(-2.0f, dot));
        if (d < best1) { best1 = d; bi1 = kb + 1; }
        unpack2(a12, lo, hi); dot = __fadd_rn(lo, hi);
        d = __fadd_rn(__fadd_rn(xsqb, eq2), __fmul_rn(-2.0f, dot));
        if (d < best1) { best1 = d; bi1 = kb + 2; }
        unpack2(a13, lo, hi); dot = __fadd_rn(lo, hi);
        d = __fadd_rn(__fadd_rn(xsqb, eq3), __fmul_rn(-2.0f, dot));
        if (d < best1) { best1 = d; bi1 = kb + 3; }
    }

    // Gather winning rows (coalesced per channel).
    {
        const int b0 = p0 >> 12, hw0 = p0 & 4095;
        float* op = out + (size_t)b0 * VQ_D * VQ_HW + hw0;
        const float* eb = es + bi0 * VQ_D;
        #pragma unroll
        for (int c = 0; c < VQ_D; c++) op[(size_t)c * VQ_HW] = eb[c];
    }
    {
        const int b1 = p1 >> 12, hw1 = p1 & 4095;
        float* op = out + (size_t)b1 * VQ_D * VQ_HW + hw1;
        const float* eb = es + bi1 * VQ_D;
        #pragma unroll
        for (int c = 0; c < VQ_D; c++) op[(size_t)c * VQ_HW] = eb[c];
    }
}

extern "C" void kernel_launch(void* const* d_in, const int* in_sizes, int n_in,
                              void* d_out, int out_size) {
    (void)in_sizes; (void)n_in; (void)out_size;
    const float* x   = (const float*)d_in[0];
    const float* emb = (const float*)d_in[1];
    float* out = (float*)d_out;

    cudaFuncSetAttribute(vq_kernel, cudaFuncAttributeMaxDynamicSharedMemorySize,
                         VQ_SMEM);

    vq_kernel<<<VQ_HALF / VQ_THREADS, VQ_THREADS, VQ_SMEM>>>(x, emb, out);
}